// round 2
// baseline (speedup 1.0000x reference)
#include <cuda_runtime.h>
#include <math.h>

// Problem constants (fixed shapes per reference)
#define NN 400000
#define EE 3200000
#define S_SEG 1200
#define B_IMG 8
#define C_FIN 64

// ---------------- device scratch (static globals; no allocation) ----------------
__device__ float  g_bufA[(size_t)NN * 64];   // aggregated (pre-BN) layer output
__device__ float  g_bufB[(size_t)NN * 64];   // gemm output t
__device__ float  g_dis[NN];                 // rsqrt(deg)
__device__ double g_stats[128];              // per-channel sum / sumsq
__device__ float  g_scale[64];
__device__ float  g_shift[64];
__device__ float  g_segfeat[S_SEG * 256];    // [mean|min|max|std] per segment
__device__ float  g_proj[S_SEG * 64];

// ---------------- degree / norm ----------------
__global__ void k_deg_init(int n) {
    int i = blockIdx.x * blockDim.x + threadIdx.x;
    if (i < n) g_dis[i] = 1.0f;  // self-loop
}
__global__ void k_deg_accum(const int* __restrict__ dst, int e) {
    int i = blockIdx.x * blockDim.x + threadIdx.x;
    if (i < e) atomicAdd(&g_dis[dst[i]], 1.0f);
}
__global__ void k_deg_fin(int n) {
    int i = blockIdx.x * blockDim.x + threadIdx.x;
    if (i < n) g_dis[i] = rsqrtf(g_dis[i]);
}

// ---------------- GEMM: t = act(affine(h)) @ W ----------------
// BN=false: read raw input pointer xin (layer 0). BN=true: read g_bufA and
// apply scale/shift (+ReLU) from previous layer's BN.
template<int FI, int FO, bool BN>
__global__ void k_gemm(const float* __restrict__ xin, const float* __restrict__ W, int n) {
    constexpr int NPB = 256 / FO;
    __shared__ float Ws[FI * FO];
    __shared__ float xs[NPB * FI];
    int tid = threadIdx.x;
    for (int i = tid; i < FI * FO; i += 256) Ws[i] = W[i];
    int base = blockIdx.x * NPB;
    for (int i = tid; i < NPB * FI; i += 256) {
        int ln = i / FI, k = i - ln * FI;
        int node = base + ln;
        float v = 0.f;
        if (node < n) {
            if (BN) {
                v = g_bufA[(size_t)node * FI + k];
                v = fmaxf(fmaf(g_scale[k], v, g_shift[k]), 0.f);
            } else {
                v = xin[(size_t)node * FI + k];
            }
        }
        xs[i] = v;
    }
    __syncthreads();
    int c = tid % FO, ln = tid / FO;
    int node = base + ln;
    if (node < n) {
        float acc = 0.f;
        #pragma unroll
        for (int k = 0; k < FI; k++)
            acc = fmaf(xs[ln * FI + k], Ws[k * FO + c], acc);
        g_bufB[(size_t)node * FO + c] = acc;
    }
}

// ---------------- self-loop init: agg = t * dis^2 ----------------
template<int FO>
__global__ void k_selfloop(int n) {
    long long idx = (long long)blockIdx.x * blockDim.x + threadIdx.x;
    if (idx >= (long long)n * FO) return;
    int node = (int)(idx / FO);
    float d = g_dis[node];
    g_bufA[idx] = g_bufB[idx] * d * d;
}

// ---------------- edge scatter: agg[dst] += t[src] * dis[src]*dis[dst] ----------------
template<int FO>
__global__ void k_scatter(const int* __restrict__ src, const int* __restrict__ dst, int e) {
    long long idx = (long long)blockIdx.x * blockDim.x + threadIdx.x;
    if (idx >= (long long)e * FO) return;
    int eid = (int)(idx >> __builtin_ctz(FO));
    int c   = (int)(idx & (FO - 1));
    int s = src[eid], d = dst[eid];
    float w = g_dis[s] * g_dis[d];
    atomicAdd(&g_bufA[(size_t)d * FO + c], g_bufB[(size_t)s * FO + c] * w);
}

// ---------------- BN stats ----------------
__global__ void k_statzero() {
    int i = threadIdx.x;
    if (i < 128) g_stats[i] = 0.0;
}
template<int FO>
__global__ void k_stats(int n) {
    __shared__ double ss[64], ss2[64];
    int tid = threadIdx.x;
    if (tid < FO) { ss[tid] = 0.0; ss2[tid] = 0.0; }
    __syncthreads();
    int c = tid % FO;
    int colPerBlk = blockDim.x / FO;
    int colId = blockIdx.x * colPerBlk + tid / FO;
    int colThreads = colPerBlk * gridDim.x;
    double s = 0.0, s2 = 0.0;
    for (int r = colId; r < n; r += colThreads) {
        double v = (double)g_bufA[(size_t)r * FO + c];
        s += v; s2 += v * v;
    }
    atomicAdd(&ss[c], s);
    atomicAdd(&ss2[c], s2);
    __syncthreads();
    if (tid < FO) {
        atomicAdd(&g_stats[tid], ss[tid]);
        atomicAdd(&g_stats[64 + tid], ss2[tid]);
    }
}
// scale = g*rsqrt(var+eps); shift = be - scale*mean   (bias b cancels in BN)
__global__ void k_bnfin(const float* __restrict__ g, const float* __restrict__ be,
                        int n, int fo) {
    int c = threadIdx.x;
    if (c >= fo) return;
    double mean = g_stats[c] / n;
    double var  = g_stats[64 + c] / n - mean * mean;
    float rs = rsqrtf((float)var + 1e-5f);
    float sc = g[c] * rs;
    g_scale[c] = sc;
    g_shift[c] = be[c] - sc * (float)mean;
}

// ---------------- segment multi-aggregation (batch_idx sorted) ----------------
__global__ void k_segagg(const int* __restrict__ bidx, int n) {
    int s = blockIdx.x;   // 0..S_SEG-1
    int c = threadIdx.x;  // 0..63
    int lo = 0, hi = n;
    while (lo < hi) { int m = (lo + hi) >> 1; if (bidx[m] < s) lo = m + 1; else hi = m; }
    int start = lo;
    hi = n;
    while (lo < hi) { int m = (lo + hi) >> 1; if (bidx[m] < s + 1) lo = m + 1; else hi = m; }
    int end = lo;
    float sc = g_scale[c], sh = g_shift[c];
    double sum = 0.0, sum2 = 0.0;
    float mn = INFINITY, mx = -INFINITY;
    for (int r = start; r < end; r++) {
        float v = fmaf(sc, g_bufA[(size_t)r * 64 + c], sh);
        sum += v; sum2 += (double)v * v;
        mn = fminf(mn, v); mx = fmaxf(mx, v);
    }
    float cnt = fmaxf((float)(end - start), 1.0f);
    float mean = (float)(sum / cnt);
    float var  = (float)(sum2 / cnt) - mean * mean;
    float stdv = sqrtf(fmaxf(var, 0.f) + 1e-5f);
    g_segfeat[s * 256 + c]        = mean;
    g_segfeat[s * 256 + 64 + c]   = mn;
    g_segfeat[s * 256 + 128 + c]  = mx;
    g_segfeat[s * 256 + 192 + c]  = stdv;
}

// ---------------- projection: [S,256] @ Wp[256,64] + bp ----------------
__global__ void k_proj(const float* __restrict__ Wp, const float* __restrict__ bp) {
    int idx = blockIdx.x * blockDim.x + threadIdx.x;
    if (idx >= S_SEG * 64) return;
    int s = idx >> 6, c = idx & 63;
    float acc = bp[c];
    const float* f = &g_segfeat[s * 256];
    #pragma unroll 8
    for (int k = 0; k < 256; k++)
        acc = fmaf(f[k], Wp[k * 64 + c], acc);
    g_proj[idx] = acc;
}

// ---------------- pack: out[b,c,j,i] = proj[offs[b] + i*14+j, c] (masked) ----------------
__global__ void k_pack(const int* __restrict__ num_sp, float* __restrict__ out) {
    int idx = blockIdx.x * blockDim.x + threadIdx.x;
    if (idx >= B_IMG * 64 * 196) return;
    int b   = idx / (64 * 196);
    int rem = idx - b * (64 * 196);
    int c   = rem / 196;
    int ji  = rem - c * 196;
    int j = ji / 14, ii = ji - j * 14;
    int p = ii * 14 + j;
    int ns = num_sp[b];
    int off = 0;
    for (int q = 0; q < b; q++) off += num_sp[q];
    float v = 0.f;
    if (p < ns) {
        int row = off + p;
        if (row > S_SEG - 1) row = S_SEG - 1;
        v = g_proj[row * 64 + c];
    }
    out[idx] = v;
}

// ---------------- host orchestration ----------------
template<int FI, int FO, bool BN>
static void run_layer(const float* xin, const float* W,
                      const float* g, const float* be, int n, int e,
                      const int* src, const int* dst) {
    constexpr int NPB = 256 / FO;
    k_gemm<FI, FO, BN><<<(n + NPB - 1) / NPB, 256>>>(xin, W, n);
    long long tot = (long long)n * FO;
    k_selfloop<FO><<<(unsigned)((tot + 255) / 256), 256>>>(n);
    long long etot = (long long)e * FO;
    k_scatter<FO><<<(unsigned)((etot + 255) / 256), 256>>>(src, dst, e);
    k_statzero<<<1, 128>>>();
    k_stats<FO><<<296, 256>>>(n);
    k_bnfin<<<1, 64>>>(g, be, n, FO);
}

extern "C" void kernel_launch(void* const* d_in, const int* in_sizes, int n_in,
                              void* d_out, int out_size) {
    const float* x        = (const float*)d_in[0];
    const int*   ei       = (const int*)d_in[1];
    const int*   batchidx = (const int*)d_in[2];
    const int*   num_sp   = (const int*)d_in[3];
    const int n = in_sizes[2];
    const int e = in_sizes[1] / 2;
    const int* src = ei;
    const int* dst = ei + e;

    const float* W[5], *g[5], *be[5];
    for (int i = 0; i < 5; i++) {
        W[i]  = (const float*)d_in[4 + 4 * i];
        g[i]  = (const float*)d_in[6 + 4 * i];
        be[i] = (const float*)d_in[7 + 4 * i];
    }
    const float* Wp = (const float*)d_in[24];
    const float* bp = (const float*)d_in[25];
    float* out = (float*)d_out;

    // degrees / normalization
    k_deg_init<<<(n + 255) / 256, 256>>>(n);
    k_deg_accum<<<(e + 255) / 256, 256>>>(dst, e);
    k_deg_fin<<<(n + 255) / 256, 256>>>(n);

    // 5 GCN layers (BN folded into affine applied on next read)
    run_layer<24,  8, false>(x,       W[0], g[0], be[0], n, e, src, dst);
    run_layer< 8, 16, true >(nullptr, W[1], g[1], be[1], n, e, src, dst);
    run_layer<16, 32, true >(nullptr, W[2], g[2], be[2], n, e, src, dst);
    run_layer<32, 64, true >(nullptr, W[3], g[3], be[3], n, e, src, dst);
    run_layer<64, 64, true >(nullptr, W[4], g[4], be[4], n, e, src, dst);

    // segment aggregation (applies layer-5 BN affine, no ReLU)
    k_segagg<<<S_SEG, 64>>>(batchidx, n);
    k_proj<<<(S_SEG * 64 + 255) / 256, 256>>>(Wp, bp);
    k_pack<<<(B_IMG * 64 * 196 + 255) / 256, 256>>>(num_sp, out);
}

// round 3
// speedup vs baseline: 2.2508x; 2.2508x over previous
#include <cuda_runtime.h>
#include <math.h>

// Problem constants (fixed shapes per reference)
#define NN 400000
#define EE 3200000
#define S_SEG 1200
#define B_IMG 8

// ---------------- device scratch (static globals; no allocation) ----------------
__device__ __align__(16) float  g_bufA[(size_t)NN * 64];   // h (post-agg, pre-BN-affine)
__device__ __align__(16) float  g_bufB[(size_t)NN * 64];   // t * dis[node]
__device__ float  g_dis[NN];                 // rsqrt(deg)
__device__ int    g_degi[NN];                // integer in-degree (incl self-loop later)
__device__ int    g_rowptr[NN + 1];
__device__ int    g_cursor[NN];
__device__ int    g_csr[EE];                 // src indices grouped by dst
__device__ int    g_bsums[512];
__device__ double g_stats[128];              // per-channel sum / sumsq
__device__ float  g_scale[64];
__device__ float  g_shift[64];
__device__ float  g_segfeat[S_SEG * 256];    // [mean|min|max|std] per segment
__device__ float  g_proj[S_SEG * 64];

// ---------------- degree / CSR build ----------------
__global__ void k_zero_nodes(int n) {
    int i = blockIdx.x * blockDim.x + threadIdx.x;
    if (i < n) { g_degi[i] = 0; g_cursor[i] = 0; }
}
__global__ void k_deg_count(const int* __restrict__ dst, int e) {
    int i = blockIdx.x * blockDim.x + threadIdx.x;
    if (i < e) atomicAdd(&g_degi[dst[i]], 1);
}
__global__ void k_deg_fin(int n) {
    int i = blockIdx.x * blockDim.x + threadIdx.x;
    if (i < n) g_dis[i] = rsqrtf((float)(g_degi[i] + 1));  // +1 self loop
}

#define SCAN_CHUNK 1024
// block-local exclusive scan of degi -> rowptr, block totals to g_bsums
__global__ void k_scan1(int n) {
    __shared__ int sh[256];
    int base = blockIdx.x * SCAN_CHUNK;
    int t = threadIdx.x;
    int v[4]; int loc = 0;
    #pragma unroll
    for (int k = 0; k < 4; k++) {
        int i = base + t * 4 + k;
        v[k] = (i < n) ? g_degi[i] : 0;
        loc += v[k];
    }
    sh[t] = loc;
    __syncthreads();
    for (int off = 1; off < 256; off <<= 1) {
        int x = sh[t];
        int y = (t >= off) ? sh[t - off] : 0;
        __syncthreads();
        sh[t] = x + y;
        __syncthreads();
    }
    int excl = (t == 0) ? 0 : sh[t - 1];
    if (t == 255) g_bsums[blockIdx.x] = sh[255];
    int run = excl;
    #pragma unroll
    for (int k = 0; k < 4; k++) {
        int i = base + t * 4 + k;
        if (i < n) g_rowptr[i] = run;
        run += v[k];
    }
}
__global__ void k_scan2(int nb) {
    __shared__ int sh[512];
    int t = threadIdx.x;
    sh[t] = (t < nb) ? g_bsums[t] : 0;
    __syncthreads();
    for (int off = 1; off < 512; off <<= 1) {
        int x = sh[t];
        int y = (t >= off) ? sh[t - off] : 0;
        __syncthreads();
        sh[t] = x + y;
        __syncthreads();
    }
    if (t < nb) g_bsums[t] = (t == 0) ? 0 : sh[t - 1];
}
__global__ void k_scan3(int n, int e) {
    int base = blockIdx.x * SCAN_CHUNK;
    int add = g_bsums[blockIdx.x];
    int t = threadIdx.x;
    #pragma unroll
    for (int k = 0; k < 4; k++) {
        int i = base + t * 4 + k;
        if (i < n) g_rowptr[i] += add;
    }
    if (blockIdx.x == 0 && t == 0) g_rowptr[n] = e;
}
__global__ void k_fill(const int* __restrict__ src, const int* __restrict__ dst, int e) {
    int i = blockIdx.x * blockDim.x + threadIdx.x;
    if (i < e) {
        int d = dst[i];
        int p = atomicAdd(&g_cursor[d], 1);
        g_csr[g_rowptr[d] + p] = src[i];
    }
}

// ---------------- GEMM: t~ = (act(affine(h)) @ W) * dis[node] ----------------
template<int FI, int FO, bool BN>
__global__ void k_gemm(const float* __restrict__ xin, const float* __restrict__ W, int n) {
    constexpr int NPB = 256 / FO;
    __shared__ float Ws[FI * FO];
    __shared__ float xs[NPB * FI];
    int tid = threadIdx.x;
    for (int i = tid; i < FI * FO; i += 256) Ws[i] = W[i];
    int base = blockIdx.x * NPB;
    for (int i = tid; i < NPB * FI; i += 256) {
        int ln = i / FI, k = i - ln * FI;
        int node = base + ln;
        float v = 0.f;
        if (node < n) {
            if (BN) {
                v = g_bufA[(size_t)node * FI + k];
                v = fmaxf(fmaf(g_scale[k], v, g_shift[k]), 0.f);
            } else {
                v = xin[(size_t)node * FI + k];
            }
        }
        xs[i] = v;
    }
    __syncthreads();
    int c = tid % FO, ln = tid / FO;
    int node = base + ln;
    if (node < n) {
        float acc = 0.f;
        #pragma unroll
        for (int k = 0; k < FI; k++)
            acc = fmaf(xs[ln * FI + k], Ws[k * FO + c], acc);
        g_bufB[(size_t)node * FO + c] = acc * g_dis[node];
    }
}

// ---------------- CSR gather + self loop + dis scale + fused BN stats ----------------
__global__ void k_statzero() {
    int i = threadIdx.x;
    if (i < 128) g_stats[i] = 0.0;
}
template<int FO>
__global__ void k_agg(int n) {
    constexpr int TPN = FO / 4;        // threads per node (float4)
    constexpr int NPB = 256 / TPN;     // nodes per block per iter
    __shared__ double ss[FO], ss2[FO];
    int tid = threadIdx.x;
    if (tid < FO) { ss[tid] = 0.0; ss2[tid] = 0.0; }
    __syncthreads();
    int grp = tid / TPN, lane = tid % TPN;
    const float4* in = (const float4*)g_bufB;
    float4* outb = (float4*)g_bufA;
    double l0 = 0, l1 = 0, l2 = 0, l3 = 0;
    double m0 = 0, m1 = 0, m2 = 0, m3 = 0;
    for (int d = blockIdx.x * NPB + grp; d < n; d += gridDim.x * NPB) {
        float4 acc = in[(size_t)d * TPN + lane];   // self-loop term (t~[d])
        int beg = g_rowptr[d], end = g_rowptr[d + 1];
        for (int j = beg; j < end; j++) {
            int s = g_csr[j];
            float4 v = in[(size_t)s * TPN + lane];
            acc.x += v.x; acc.y += v.y; acc.z += v.z; acc.w += v.w;
        }
        float dd = g_dis[d];
        acc.x *= dd; acc.y *= dd; acc.z *= dd; acc.w *= dd;
        outb[(size_t)d * TPN + lane] = acc;
        l0 += acc.x; l1 += acc.y; l2 += acc.z; l3 += acc.w;
        m0 += (double)acc.x * acc.x; m1 += (double)acc.y * acc.y;
        m2 += (double)acc.z * acc.z; m3 += (double)acc.w * acc.w;
    }
    int c = lane * 4;
    atomicAdd(&ss[c + 0], l0); atomicAdd(&ss2[c + 0], m0);
    atomicAdd(&ss[c + 1], l1); atomicAdd(&ss2[c + 1], m1);
    atomicAdd(&ss[c + 2], l2); atomicAdd(&ss2[c + 2], m2);
    atomicAdd(&ss[c + 3], l3); atomicAdd(&ss2[c + 3], m3);
    __syncthreads();
    if (tid < FO) {
        atomicAdd(&g_stats[tid], ss[tid]);
        atomicAdd(&g_stats[64 + tid], ss2[tid]);
    }
}

// scale = g*rsqrt(var+eps); shift = be - scale*mean   (bias b cancels in BN)
__global__ void k_bnfin(const float* __restrict__ g, const float* __restrict__ be,
                        int n, int fo) {
    int c = threadIdx.x;
    if (c >= fo) return;
    double mean = g_stats[c] / n;
    double var  = g_stats[64 + c] / n - mean * mean;
    float rs = rsqrtf((float)var + 1e-5f);
    float sc = g[c] * rs;
    g_scale[c] = sc;
    g_shift[c] = be[c] - sc * (float)mean;
}

// ---------------- segment multi-aggregation (batch_idx sorted) ----------------
__global__ void k_segagg(const int* __restrict__ bidx, int n) {
    int s = blockIdx.x;   // 0..S_SEG-1
    int tid = threadIdx.x;
    int c = tid & 63, rr = tid >> 6;     // 4 row groups x 64 channels
    int lo = 0, hi = n;
    while (lo < hi) { int m = (lo + hi) >> 1; if (bidx[m] < s) lo = m + 1; else hi = m; }
    int start = lo;
    hi = n;
    while (lo < hi) { int m = (lo + hi) >> 1; if (bidx[m] < s + 1) lo = m + 1; else hi = m; }
    int end = lo;
    float sc = g_scale[c], sh = g_shift[c];
    double sum = 0.0, sum2 = 0.0;
    float mn = INFINITY, mx = -INFINITY;
    for (int r = start + rr; r < end; r += 4) {
        float v = fmaf(sc, g_bufA[(size_t)r * 64 + c], sh);
        sum += v; sum2 += (double)v * v;
        mn = fminf(mn, v); mx = fmaxf(mx, v);
    }
    __shared__ double s1[256], s2[256];
    __shared__ float smn[256], smx[256];
    s1[tid] = sum; s2[tid] = sum2; smn[tid] = mn; smx[tid] = mx;
    __syncthreads();
    if (rr == 0) {
        #pragma unroll
        for (int k = 1; k < 4; k++) {
            sum += s1[tid + 64 * k]; sum2 += s2[tid + 64 * k];
            mn = fminf(mn, smn[tid + 64 * k]); mx = fmaxf(mx, smx[tid + 64 * k]);
        }
        float cnt = fmaxf((float)(end - start), 1.0f);
        float mean = (float)(sum / cnt);
        float var  = (float)(sum2 / cnt) - mean * mean;
        float stdv = sqrtf(fmaxf(var, 0.f) + 1e-5f);
        g_segfeat[s * 256 + c]        = mean;
        g_segfeat[s * 256 + 64 + c]   = mn;
        g_segfeat[s * 256 + 128 + c]  = mx;
        g_segfeat[s * 256 + 192 + c]  = stdv;
    }
}

// ---------------- projection: [S,256] @ Wp[256,64] + bp ----------------
__global__ void k_proj(const float* __restrict__ Wp, const float* __restrict__ bp) {
    int idx = blockIdx.x * blockDim.x + threadIdx.x;
    if (idx >= S_SEG * 64) return;
    int s = idx >> 6, c = idx & 63;
    float acc = bp[c];
    const float* f = &g_segfeat[s * 256];
    #pragma unroll 8
    for (int k = 0; k < 256; k++)
        acc = fmaf(f[k], Wp[k * 64 + c], acc);
    g_proj[idx] = acc;
}

// ---------------- pack: out[b,c,j,i] = proj[offs[b] + i*14+j, c] (masked) ----------------
__global__ void k_pack(const int* __restrict__ num_sp, float* __restrict__ out) {
    int idx = blockIdx.x * blockDim.x + threadIdx.x;
    if (idx >= B_IMG * 64 * 196) return;
    int b   = idx / (64 * 196);
    int rem = idx - b * (64 * 196);
    int c   = rem / 196;
    int ji  = rem - c * 196;
    int j = ji / 14, ii = ji - j * 14;
    int p = ii * 14 + j;
    int ns = num_sp[b];
    int off = 0;
    for (int q = 0; q < b; q++) off += num_sp[q];
    float v = 0.f;
    if (p < ns) {
        int row = off + p;
        if (row > S_SEG - 1) row = S_SEG - 1;
        v = g_proj[row * 64 + c];
    }
    out[idx] = v;
}

// ---------------- host orchestration ----------------
template<int FI, int FO, bool BN>
static void run_layer(const float* xin, const float* W,
                      const float* g, const float* be, int n) {
    constexpr int NPB = 256 / FO;
    k_gemm<FI, FO, BN><<<(n + NPB - 1) / NPB, 256>>>(xin, W, n);
    k_statzero<<<1, 128>>>();
    k_agg<FO><<<592, 256>>>(n);
    k_bnfin<<<1, 64>>>(g, be, n, FO);
}

extern "C" void kernel_launch(void* const* d_in, const int* in_sizes, int n_in,
                              void* d_out, int out_size) {
    const float* x        = (const float*)d_in[0];
    const int*   ei       = (const int*)d_in[1];
    const int*   batchidx = (const int*)d_in[2];
    const int*   num_sp   = (const int*)d_in[3];
    const int n = in_sizes[2];
    const int e = in_sizes[1] / 2;
    const int* src = ei;
    const int* dst = ei + e;

    const float* W[5], *g[5], *be[5];
    for (int i = 0; i < 5; i++) {
        W[i]  = (const float*)d_in[4 + 4 * i];
        g[i]  = (const float*)d_in[6 + 4 * i];
        be[i] = (const float*)d_in[7 + 4 * i];
    }
    const float* Wp = (const float*)d_in[24];
    const float* bp = (const float*)d_in[25];
    float* out = (float*)d_out;

    // degrees + CSR build (once per launch; reused by all 5 layers)
    k_zero_nodes<<<(n + 255) / 256, 256>>>(n);
    k_deg_count<<<(e + 255) / 256, 256>>>(dst, e);
    k_deg_fin<<<(n + 255) / 256, 256>>>(n);
    int nb = (n + SCAN_CHUNK - 1) / SCAN_CHUNK;
    k_scan1<<<nb, 256>>>(n);
    k_scan2<<<1, 512>>>(nb);
    k_scan3<<<nb, 256>>>(n, e);
    k_fill<<<(e + 255) / 256, 256>>>(src, dst, e);

    // 5 GCN layers (BN folded into affine applied on next read; stats fused in agg)
    run_layer<24,  8, false>(x,       W[0], g[0], be[0], n);
    run_layer< 8, 16, true >(nullptr, W[1], g[1], be[1], n);
    run_layer<16, 32, true >(nullptr, W[2], g[2], be[2], n);
    run_layer<32, 64, true >(nullptr, W[3], g[3], be[3], n);
    run_layer<64, 64, true >(nullptr, W[4], g[4], be[4], n);

    // segment aggregation (applies layer-5 BN affine, no ReLU)
    k_segagg<<<S_SEG, 256>>>(batchidx, n);
    k_proj<<<(S_SEG * 64 + 255) / 256, 256>>>(Wp, bp);
    k_pack<<<(B_IMG * 64 * 196 + 255) / 256, 256>>>(num_sp, out);
}